// round 14
// baseline (speedup 1.0000x reference)
#include <cuda_runtime.h>
#include <cuda_bf16.h>

// Problem constants (fixed by the reference's setup_inputs)
#define N_NODES  100000
#define E_EDGES  1600000
#define FLOW_ITERS 10

// Persistent-kernel geometry: must be co-resident for the software grid barrier.
#define GRID 592                               // 4 blocks/SM x 148 SMs (measured best)
#define TPB  256
#define TTOT (GRID * TPB)                      // 151,552 threads
#define EPT_FULL (E_EDGES / TTOT)              // 10 full strides
#define EPT (EPT_FULL + 1)                     // 11 (last stride partial)
#define E_TAIL (E_EDGES - EPT_FULL * TTOT)     // 84,480 edges in last stride
#define NPB  169                               // nodes per block: 592*169 >= N
#define SMEM_COLS 4096                         // block col-slice cap (mean 2704, sd ~52)

// Scratch (__device__ globals; zero-initialized at module load; the persistent
// epilogue re-zeroes the accumulating ones for graph-replay determinism)
__device__ int      g_deg[N_NODES];            // out-degree (src)
__device__ int      g_degd[N_NODES];           // in-degree (dst)
__device__ int      g_row[N_NODES];            // CSR row starts (by dst)
__device__ int      g_cursor[N_NODES];
__device__ int      g_col[E_EDGES];            // CSR cols = src of each in-edge
__device__ float2   g_vd[2][N_NODES];          // {v_k, invdeg} packed per node
__device__ int      g_base;                    // atomic CSR base allocator
__device__ unsigned g_count, g_gen;            // barrier state

// Software grid barrier. gpu-scope __threadfence() emits CCTL.IVALL on sm_103a,
// so plain L1-cached loads of cross-SM data are coherent across phases
// (validated R7-R13: rel_err ~2-7e-7). Busy-spin (no nanosleep) for minimal
// wake latency. Generation-relative -> safe across graph replays.
__device__ __forceinline__ void gbar() {
    __syncthreads();
    if (threadIdx.x == 0) {
        unsigned old = *(volatile unsigned*)&g_gen;
        __threadfence();
        if (atomicAdd(&g_count, 1u) == GRID - 1) {
            g_count = 0;
            __threadfence();
            atomicAdd(&g_gen, 1u);
        } else {
            while (*(volatile unsigned*)&g_gen == old) { }
        }
        __threadfence();
    }
    __syncthreads();
}

// ---------------------------------------------------------------------------
// Persistent fused kernel, CSR formulation, balanced + prefetched row pass:
//   v_0 = invdeg;  v_k = invdeg * relu(A @ v_{k-1} - d0)   (A = in-adjacency)
//   flow = v_10[src],  fw = invdeg[src]  (both from ONE float2 gather)
// Each block owns NPB consecutive nodes. CSR col slice + edge->owner map in
// SHARED (staged once). Each iteration all 256 threads gather an even slice
// with 8-wide software prefetch (MLP~8), run-coalesce into s_acc, owners
// apply the node update. 13 global barriers total.
// ---------------------------------------------------------------------------
__global__ void __launch_bounds__(TPB, 4)
k_persist(const int* __restrict__ src_g, const int* __restrict__ dst_g,
          const float* __restrict__ d0, float* __restrict__ out)
{
    __shared__ int            s_col[SMEM_COLS];
    __shared__ unsigned short s_node[SMEM_COLS];
    __shared__ int            s_scan[TPB];
    __shared__ float          s_acc[NPB];
    __shared__ int            s_base_sh;
    __shared__ float          s_wred[TPB / 32];

    const int b   = blockIdx.x;
    const int t   = threadIdx.x;
    const int tid = b * TPB + t;
    float* __restrict__ flow_out = out + 1;
    float* __restrict__ fw_out   = out + 1 + E_EDGES;
    const bool tail_ok = (tid < E_TAIL);

    // Edge payload in registers (esrc stays live to the epilogue; edst dies
    // after the CSR fill, freeing registers for the prefetch batch).
    int esrc[EPT], edst[EPT];
#pragma unroll
    for (int k = 0; k < EPT_FULL; k++) {
        esrc[k] = __ldg(src_g + tid + k * TTOT);
        edst[k] = __ldg(dst_g + tid + k * TTOT);
    }
    esrc[EPT_FULL] = tail_ok ? __ldg(src_g + tid + EPT_FULL * TTOT) : 0;
    edst[EPT_FULL] = tail_ok ? __ldg(dst_g + tid + EPT_FULL * TTOT) : 0;

    // Phase 1: histograms (g_deg/g_degd zero at entry: zero-init on first run,
    // re-zeroed in epilogue for replays). Also reset cost accumulator.
    if (tid == 0) out[0] = 0.0f;
#pragma unroll
    for (int k = 0; k < EPT_FULL; k++) {
        atomicAdd(&g_deg[esrc[k]], 1);
        atomicAdd(&g_degd[edst[k]], 1);
    }
    if (tail_ok) {
        atomicAdd(&g_deg[esrc[EPT_FULL]], 1);
        atomicAdd(&g_degd[edst[EPT_FULL]], 1);
    }
    gbar();                                            // barrier 1

    // Phase 2 (merged scan): per-block scan of owned in-degrees; block claims
    // a contiguous CSR range via one atomicAdd on g_base. invdeg = 1/(deg+1e-9)
    // is bitwise identical to the reference segment softmax (equal scores per
    // segment -> exp==1, den==deg exactly); v_0 = invdeg.
    const int  n   = b * NPB + t;                      // owned node
    const bool own = (t < NPB) && (n < N_NODES);
    int my_deg = own ? g_degd[n] : 0;
    {
        s_scan[t] = my_deg;
        __syncthreads();
#pragma unroll
        for (int off = 1; off < TPB; off <<= 1) {
            int add = (t >= off) ? s_scan[t - off] : 0;
            __syncthreads();
            s_scan[t] += add;
            __syncthreads();
        }
        if (t == 0) s_base_sh = atomicAdd(&g_base, s_scan[TPB - 1]);
        __syncthreads();
    }
    const int blk_base = s_base_sh;
    const int blk_tot  = s_scan[TPB - 1];
    const int my_loc   = s_scan[t] - my_deg;           // local CSR offset
    const bool use_smem = (blk_tot <= SMEM_COLS);
    if (own) {
        int rs = blk_base + my_loc;
        g_row[n]    = rs;
        g_cursor[n] = rs;
    }
    if (tid < N_NODES) {
        float iv = 1.0f / ((float)g_deg[tid] + 1e-9f);
        g_vd[0][tid] = make_float2(iv, iv);            // v_0 = invdeg, .y = invdeg
        g_vd[1][tid] = make_float2(0.0f, iv);          // parity buffer .y = invdeg
    }
    gbar();                                            // barrier 2

    // Phase 3: CSR fill (the only per-edge atomics, paid once).
    // Overlap: owners also write the block-local edge->owner map (pure smem).
    if (own && use_smem) {
        for (int j = 0; j < my_deg; ++j)
            s_node[my_loc + j] = (unsigned short)t;
    }
#pragma unroll
    for (int k = 0; k < EPT; k++) {
        bool ok = (k < EPT_FULL) || tail_ok;
        if (ok) {
            int p = atomicAdd(&g_cursor[edst[k]], 1);
            g_col[p] = esrc[k];
        }
    }
    gbar();                                            // barrier 3

    // Stage this block's contiguous col slice into SHARED (once, reused x10),
    // hoist per-node metadata to registers, compute this thread's edge slice.
    if (use_smem) {
        for (int i = t; i < blk_tot; i += TPB) s_col[i] = g_col[blk_base + i];
    }
    float my_iv = 0.0f, my_d0 = 0.0f;
    if (own) {
        my_iv = g_vd[0][n].y;                          // invdeg
        my_d0 = __ldg(&d0[n]);
    }
    const int lo = (blk_tot * t) >> 8;                 // even 1/256 edge slice
    const int hi = (blk_tot * (t + 1)) >> 8;
    __syncthreads();

    // Phases 4..13: balanced row passes with 8-wide software prefetch.
    // Batch-issue 8 independent gathers (MLP~8), then run-coalesce into s_acc
    // via smem atomics; owners finish the node update.
    for (int it = 1; it <= FLOW_ITERS; ++it) {
        const float2* __restrict__ vp = g_vd[(it - 1) & 1];
        float2* __restrict__ vc = g_vd[it & 1];

        if (t < NPB) s_acc[t] = 0.0f;
        __syncthreads();

        if (use_smem) {
            float run = 0.0f;
            int   cur = -1;
            int   i   = lo;
            while (i < hi) {
                int m = hi - i; if (m > 8) m = 8;
                float vals[8];
#pragma unroll
                for (int j = 0; j < 8; ++j)
                    if (j < m) vals[j] = vp[s_col[i + j]].x;
#pragma unroll
                for (int j = 0; j < 8; ++j) {
                    if (j < m) {
                        int nd = s_node[i + j];
                        if (nd != cur) {
                            if (cur >= 0) atomicAdd(&s_acc[cur], run);
                            cur = nd;
                            run = vals[j];
                        } else {
                            run += vals[j];
                        }
                    }
                }
                i += m;
            }
            if (cur >= 0) atomicAdd(&s_acc[cur], run);
        } else if (own) {                              // pathological fallback
            int s = blk_base + my_loc, e = s + my_deg;
            float sum = 0.0f;
            for (int i = s; i < e; ++i) sum += vp[g_col[i]].x;
            s_acc[t] = sum;
        }
        __syncthreads();

        if (own) {
            float vk = my_iv * fmaxf(s_acc[t] - my_d0, 0.0f);
            __stcg(&vc[n], make_float2(vk, my_iv));
        }
        gbar();                                        // barriers 4..13
    }

    // Epilogue: ONE float2 gather yields flow (v_10) AND fw (invdeg).
    // Also re-zero the accumulating globals for the next graph replay.
    const float2* __restrict__ vf = g_vd[FLOW_ITERS & 1];
    float acc = 0.0f;
#pragma unroll
    for (int k = 0; k < EPT_FULL; k++) {
        float2 r = vf[esrc[k]];
        flow_out[tid + k * TTOT] = r.x;
        fw_out[tid + k * TTOT]   = r.y;
        acc += r.x * r.x;
    }
    if (tail_ok) {
        float2 r = vf[esrc[EPT_FULL]];
        flow_out[tid + EPT_FULL * TTOT] = r.x;
        fw_out[tid + EPT_FULL * TTOT]   = r.y;
        acc += r.x * r.x;
    }
    if (tid < N_NODES) { g_deg[tid] = 0; g_degd[tid] = 0; }
    if (tid == 0) g_base = 0;

#pragma unroll
    for (int o = 16; o > 0; o >>= 1)
        acc += __shfl_down_sync(0xFFFFFFFF, acc, o);
    int lane = t & 31, wid = t >> 5;
    if (lane == 0) s_wred[wid] = acc;
    __syncthreads();
    if (wid == 0) {
        acc = (lane < TPB / 32) ? s_wred[lane] : 0.0f;
#pragma unroll
        for (int o = 16; o > 0; o >>= 1)
            acc += __shfl_down_sync(0xFFFFFFFF, acc, o);
        if (lane == 0) atomicAdd(out, acc);
    }
}

// ======================= Fallback path (proven R3 kernels) ==================
__device__ float g_inflow2[2][N_NODES];

__global__ void k_zero(float* __restrict__ out0) {
    int i = blockIdx.x * blockDim.x + threadIdx.x;
    if (i < N_NODES) {
        g_deg[i] = 0;
        g_inflow2[0][i] = 0.0f;
        g_inflow2[1][i] = 0.0f;
    }
    if (i == 0) *out0 = 0.0f;
}

__global__ void k_count(const int* __restrict__ src, int E) {
    int i = blockIdx.x * blockDim.x + threadIdx.x;
    if (i < E) atomicAdd(&g_deg[__ldg(&src[i])], 1);
}

__global__ void k_init(const int* __restrict__ src,
                       float* __restrict__ flow,
                       float* __restrict__ fw, int E) {
    int i = blockIdx.x * blockDim.x + threadIdx.x;
    if (i < E) {
        float den = (float)g_deg[__ldg(&src[i])] + 1e-9f;
        float f = 1.0f / den;
        fw[i]   = f;
        flow[i] = f;
    }
}

__global__ void k_scatter(const int* __restrict__ dst,
                          const float* __restrict__ flow, int E, int buf) {
    int i2 = blockIdx.x * blockDim.x + threadIdx.x;
    int i  = i2 * 2;
    if (i + 1 < E) {
        int2  d  = *(const int2*)(dst + i);
        float f0 = __ldg(&flow[i]);
        float f1 = __ldg(&flow[i + 1]);
        atomicAdd(&g_inflow2[buf][d.x], f0);
        atomicAdd(&g_inflow2[buf][d.y], f1);
    } else if (i < E) {
        atomicAdd(&g_inflow2[buf][__ldg(&dst[i])], __ldg(&flow[i]));
    }
}

__global__ void k_apply(const int* __restrict__ src,
                        const float* __restrict__ fw,
                        const float* __restrict__ d0,
                        float* __restrict__ flow, int E, int buf) {
    int i2 = blockIdx.x * blockDim.x + threadIdx.x;
    int i  = i2 * 2;
    const float* __restrict__ infl = g_inflow2[buf];
    if (i + 1 < E) {
        int2  s  = *(const int2*)(src + i);
        float w0 = __ldg(&fw[i]);
        float w1 = __ldg(&fw[i + 1]);
        float a0 = fmaxf(__ldg(&infl[s.x]) - __ldg(&d0[s.x]), 0.0f);
        float a1 = fmaxf(__ldg(&infl[s.y]) - __ldg(&d0[s.y]), 0.0f);
        flow[i]     = w0 * a0;
        flow[i + 1] = w1 * a1;
    } else if (i < E) {
        int s = __ldg(&src[i]);
        float a = fmaxf(__ldg(&infl[s]) - __ldg(&d0[s]), 0.0f);
        flow[i] = __ldg(&fw[i]) * a;
    }
    if (i2 < N_NODES) g_inflow2[buf ^ 1][i2] = 0.0f;
}

__global__ void k_cost(const float* __restrict__ flow, float* __restrict__ out0, int E) {
    __shared__ float warp_part[32];
    float acc = 0.0f;
    for (int i = blockIdx.x * blockDim.x + threadIdx.x; i < E;
         i += gridDim.x * blockDim.x) {
        float v = __ldg(&flow[i]);
        acc += v * v;
    }
    #pragma unroll
    for (int o = 16; o > 0; o >>= 1)
        acc += __shfl_down_sync(0xFFFFFFFF, acc, o);
    int lane = threadIdx.x & 31;
    int wid  = threadIdx.x >> 5;
    if (lane == 0) warp_part[wid] = acc;
    __syncthreads();
    if (wid == 0) {
        int nw = (blockDim.x + 31) >> 5;
        acc = (lane < nw) ? warp_part[lane] : 0.0f;
        #pragma unroll
        for (int o = 16; o > 0; o >>= 1)
            acc += __shfl_down_sync(0xFFFFFFFF, acc, o);
        if (lane == 0) atomicAdd(out0, acc);
    }
}

// ---------------------------------------------------------------------------
// Launch. Inputs: demands, node_embeddings, edge_src, edge_dst, [weights...].
// Output layout: [flow_cost(1), flow(E), fw(E)]. The GNN is provably dead
// code w.r.t. the outputs (uniform per-segment softmax scores).
// ---------------------------------------------------------------------------
extern "C" void kernel_launch(void* const* d_in, const int* in_sizes, int n_in,
                              void* d_out, int out_size) {
    const float* demands = (const float*)d_in[0];   // N x 1
    const int*   src     = (const int*)  d_in[2];   // E
    const int*   dst     = (const int*)  d_in[3];   // E
    const int E = in_sizes[2];
    const int Nn = in_sizes[0];

    float* out  = (float*)d_out;
    float* flow = out + 1;       // E floats (only 4B aligned!)
    float* fw   = out + 1 + E;   // E floats (only 4B aligned!)

    // Can the persistent kernel's GRID blocks be fully co-resident?
    bool use_persist = (E == E_EDGES && Nn == N_NODES);
    if (use_persist) {
        int dev = 0, sms = 0, occ = 0;
        cudaGetDevice(&dev);
        cudaDeviceGetAttribute(&sms, cudaDevAttrMultiProcessorCount, dev);
        cudaOccupancyMaxActiveBlocksPerMultiprocessor(&occ, k_persist, TPB, 0);
        if ((long long)occ * sms < GRID) use_persist = false;
    }

    if (use_persist) {
        k_persist<<<GRID, TPB>>>(src, dst, demands, out);
        return;
    }

    // Fallback: proven multi-kernel path.
    const int T   = 256;
    const int BE  = (E + T - 1) / T;
    const int BE2 = (E / 2 + T) / T;
    const int BN  = (N_NODES + T - 1) / T;

    k_zero<<<BN, T>>>(out);
    k_count<<<BE, T>>>(src, E);
    k_init<<<BE, T>>>(src, flow, fw, E);
    for (int it = 0; it < FLOW_ITERS; ++it) {
        int buf = it & 1;
        k_scatter<<<BE2, T>>>(dst, flow, E, buf);
        k_apply<<<BE2, T>>>(src, fw, demands, flow, E, buf);
    }
    k_cost<<<1024, 256>>>(flow, out, E);
}